// round 9
// baseline (speedup 1.0000x reference)
#include <cuda_runtime.h>
#include <stdint.h>

// SGC 2-hop: out = S^2 x W^T + b,  S = D^-1/2 (A + I) D^-1/2
// Identity: (S^2 x) W^T == S^2 (x W^T) -> project features to scalar FIRST,
// then two scalar scatter passes over edges (L2-resident accumulators).
// R7: pack (row,col) -> int2 scratch once; scatters do 4 edges/thread (MLP=4).

#define MAXN  100000
#define MAXE  600000
#define DFEAT 128
#define PROWS 8          // rows per warp in k_project
#define EPT   4          // edges per thread in k_scatter

__device__ int   g_cnt[MAXN];     // in-degree (excl. self loop)
__device__ float g_dis[MAXN];     // deg^-1/2
__device__ float g_z[MAXN];       // scalar being propagated
__device__ float g_acc[MAXN];     // scatter accumulator
__device__ int2  g_edge[MAXE];    // packed (row, col) int32
__device__ int   g_is32;          // zero-init at load; sticky (set-to-1 only)

__device__ __forceinline__ int load_idx(const void* ei, int is32, long long pos) {
    if (is32) return __ldg((const int*)ei + pos);
    return (int)__ldg((const long long*)ei + pos);
}

// ---- kernel 0: zero counts; blocks 0..15 also detect index dtype on a
// 4096-word prefix. int64 LE (<2^31) => odd 32-bit words all 0; for a real
// int32 index buffer P(one word==0)=1e-5, so 4096 words is definitive.
// Sticky flag => deterministic across graph replays.
__global__ void k_init_detect(const int* __restrict__ w, int e, int n) {
    int i = blockIdx.x * blockDim.x + threadIdx.x;
    if (i < n) g_cnt[i] = 0;
    if (i < 2048) {  // checks odd words w[2i+1], i < 2048 -> 4096-word prefix
        long long lim = 2LL * e;
        long long p = 2LL * i + 1;
        if (p < lim && __ldg(w + p) != 0) g_is32 = 1;
    }
}

// ---- kernel 1: pack (row,col) into int2 scratch + count in-degree ----
__global__ void k_pack_count(const void* __restrict__ ei, int e, int n) {
    int i = blockIdx.x * blockDim.x + threadIdx.x;
    if (i >= e) return;
    int is32 = g_is32;
    int r = load_idx(ei, is32, i);
    int c = load_idx(ei, is32, (long long)e + i);
    g_edge[i] = make_int2(r, c);
    if ((unsigned)c < (unsigned)n) atomicAdd(&g_cnt[c], 1);
}

// ---- kernel 2: y = x @ W^T, 8 rows/warp for MLP; z = dis*y; acc = z ----
__global__ void k_project(const float* __restrict__ x,
                          const float* __restrict__ W, int n) {
    int warp = (blockIdx.x * blockDim.x + threadIdx.x) >> 5;
    int lane = threadIdx.x & 31;
    int base = warp * PROWS;
    if (base >= n) return;

    int rows = n - base; if (rows > PROWS) rows = PROWS;

    float4 w = reinterpret_cast<const float4*>(W)[lane];
    const float4* xv = reinterpret_cast<const float4*>(x)
                       + (size_t)base * (DFEAT / 4) + lane;

    float4 a[PROWS];
    #pragma unroll
    for (int j = 0; j < PROWS; j++)
        if (j < rows) a[j] = xv[(size_t)j * (DFEAT / 4)];

    #pragma unroll
    for (int j = 0; j < PROWS; j++) {
        if (j >= rows) break;
        float d = a[j].x * w.x + a[j].y * w.y + a[j].z * w.z + a[j].w * w.w;
        #pragma unroll
        for (int off = 16; off > 0; off >>= 1)
            d += __shfl_down_sync(0xFFFFFFFFu, d, off);
        if (lane == 0) {
            int node = base + j;
            float dis = rsqrtf((float)(g_cnt[node] + 1));  // +1 self loop
            float z = dis * d;
            g_dis[node] = dis;
            g_z[node]   = z;
            g_acc[node] = z;   // self-loop contribution
        }
    }
}

// ---- kernel 3: acc[col] += z[row], 4 edges/thread, batched loads ----
__global__ void k_scatter(int e, int n) {
    int t = blockIdx.x * blockDim.x + threadIdx.x;
    int base = t * EPT;
    if (base >= e) return;
    int cnt = e - base; if (cnt > EPT) cnt = EPT;

    // two int4 loads = 4 packed (r,c) pairs, front-batched
    const int4* ep = reinterpret_cast<const int4*>(&g_edge[base]);
    int4 p0 = __ldg(ep);
    int4 p1 = (cnt > 2) ? __ldg(ep + 1) : make_int4(0, -1, 0, -1);
    int r[EPT] = {p0.x, p0.z, p1.x, p1.z};
    int c[EPT] = {p0.y, p0.w, p1.y, p1.w};
    if (cnt < 2) { c[1] = -1; }
    if (cnt < 4) { c[3] = -1; }

    // batched gathers (MLP=4)
    float v[EPT];
    #pragma unroll
    for (int j = 0; j < EPT; j++)
        v[j] = ((unsigned)r[j] < (unsigned)n && (unsigned)c[j] < (unsigned)n)
               ? __ldg(&g_z[r[j]]) : 0.0f;

    #pragma unroll
    for (int j = 0; j < EPT; j++)
        if ((unsigned)c[j] < (unsigned)n && v[j] != 0.0f)
            atomicAdd(&g_acc[c[j]], v[j]);
}

// ---- kernel 4: z' = dis^2 * acc; acc = z' (self loop for next hop) ----
__global__ void k_rescale(int n) {
    int i = blockIdx.x * blockDim.x + threadIdx.x;
    if (i < n) {
        float dis = g_dis[i];
        float v = dis * dis * g_acc[i];
        g_z[i]   = v;
        g_acc[i] = v;
    }
}

// ---- kernel 5: out = dis * acc + b ----
__global__ void k_finish(float* __restrict__ out,
                         const float* __restrict__ b, int n) {
    int i = blockIdx.x * blockDim.x + threadIdx.x;
    if (i < n) out[i] = g_dis[i] * g_acc[i] + b[0];
}

extern "C" void kernel_launch(void* const* d_in, const int* in_sizes, int n_in,
                              void* d_out, int out_size) {
    const float* x  = (const float*)d_in[0];
    const void*  ei = d_in[1];                 // [2, E], int32 or int64
    const float* W  = (const float*)d_in[2];
    const float* b  = (const float*)d_in[3];
    float* out = (float*)d_out;

    int n = in_sizes[0] / DFEAT;      // 100000
    int e = in_sizes[1] / 2;          // 600000
    if (e > MAXE) e = MAXE;           // scratch capacity guard

    const int T = 256;
    int gbN = (n + T - 1) / T;
    int gbE = (e + T - 1) / T;
    int nwarps = (n + PROWS - 1) / PROWS;
    int gbP = (nwarps * 32 + T - 1) / T;
    int nse = (e + EPT - 1) / EPT;
    int gbS = (nse + T - 1) / T;

    k_init_detect<<<gbN, T>>>((const int*)ei, e, n);
    k_pack_count <<<gbE, T>>>(ei, e, n);
    k_project    <<<gbP, T>>>(x, W, n);
    k_scatter    <<<gbS, T>>>(e, n);   // hop 1
    k_rescale    <<<gbN, T>>>(n);
    k_scatter    <<<gbS, T>>>(e, n);   // hop 2
    k_finish     <<<gbN, T>>>(out, b, n);
}